// round 16
// baseline (speedup 1.0000x reference)
#include <cuda_runtime.h>
#include <cuda_bf16.h>
#include <cstddef>
#include <cstdint>

#define D 128
#define MAXG 100000

// scratch (device globals — no allocation allowed)
__device__ int   g_last[MAXG];
__device__ float g_A[D * D];
__device__ float g_bp[D];
__device__ float g_p[(size_t)MAXG * D];
__device__ float g_s[(size_t)MAXG * D];
// bf16 hi/lo splits of the two B matrices, stored as b_eff[n][k]
__device__ __nv_bfloat16 g_B1h[D * D], g_B1l[D * D];
__device__ __nv_bfloat16 g_B2h[D * D], g_B2l[D * D];

// ---------------------------------------------------------------- helpers
__device__ __forceinline__ float lo_of(float v) {
    return v - __bfloat162float(__float2bfloat16(v));
}
__device__ __forceinline__ uint32_t pack2(float a, float b) {
    __nv_bfloat162 h;
    h.x = __float2bfloat16(a);
    h.y = __float2bfloat16(b);
    return *(uint32_t*)&h;
}
__device__ __forceinline__ uint32_t smem_u32(const void* p) {
    uint32_t a;
    asm("{ .reg .u64 t; cvta.to.shared.u64 t, %1; cvt.u32.u64 %0, t; }"
        : "=r"(a) : "l"(p));
    return a;
}

#define MMA_BF16(cc, a0, a1, a2, a3, b0, b1)                                  \
    asm volatile(                                                             \
        "mma.sync.aligned.m16n8k16.row.col.f32.bf16.bf16.f32 "                \
        "{%0,%1,%2,%3}, {%4,%5,%6,%7}, {%8,%9}, {%0,%1,%2,%3};"               \
        : "+f"(cc[0]), "+f"(cc[1]), "+f"(cc[2]), "+f"(cc[3])                  \
        : "r"(a0), "r"(a1), "r"(a2), "r"(a3), "r"(b0), "r"(b1))

#define LDSM_X4(r, addr)                                                      \
    asm volatile("ldmatrix.sync.aligned.m8n8.x4.shared.b16 {%0,%1,%2,%3}, [%4];" \
                 : "=r"(r[0]), "=r"(r[1]), "=r"(r[2]), "=r"(r[3])             \
                 : "r"(addr))

// -------------------------------------------------------------------------
// 1) segment boundaries
// -------------------------------------------------------------------------
__global__ void bounds_kernel(const int* __restrict__ seg, int N) {
    int i = blockIdx.x * blockDim.x + threadIdx.x;
    if (i < N) {
        int sid = seg[i];
        if (i == N - 1 || seg[i + 1] != sid) g_last[sid] = i;
    }
}

// -------------------------------------------------------------------------
// 2) A = Wq^T @ Wk, b' = bq @ Wk
// -------------------------------------------------------------------------
__global__ void prep_kernel(const float* __restrict__ Wq, const float* __restrict__ bq,
                            const float* __restrict__ Wk) {
    int t = threadIdx.x;
    if (blockIdx.x < 64) {
        int idx = blockIdx.x * 256 + t;
        int i = idx >> 7, j = idx & 127;
        float sum = 0.f;
#pragma unroll 8
        for (int d = 0; d < D; d++) sum += Wq[d * D + i] * Wk[d * D + j];
        g_A[idx] = sum;
    } else if (t < D) {
        float sum = 0.f;
#pragma unroll 8
        for (int d = 0; d < D; d++) sum += bq[d] * Wk[d * D + t];
        g_bp[t] = sum;
    }
}

// -------------------------------------------------------------------------
// 2b) bf16 hi/lo split of both B matrices (b_eff[n][k] layout)
// -------------------------------------------------------------------------
__global__ void split_kernel(const float* __restrict__ Wk) {
    int idx = blockIdx.x * 256 + threadIdx.x;
    int n = idx >> 7, k = idx & 127;
    float v1 = g_A[k * D + n];
    g_B1h[idx] = __float2bfloat16(v1);
    g_B1l[idx] = __float2bfloat16(lo_of(v1));
    float v2 = Wk[idx];
    g_B2h[idx] = __float2bfloat16(v2);
    g_B2l[idx] = __float2bfloat16(lo_of(v2));
}

// -------------------------------------------------------------------------
// Tensor-core GEMM via mma.sync + ldmatrix:
//   C[M,128] = rows(Amat) @ b_eff^T + bias
//   3-term bf16 split (hi*hi + lo*hi + hi*lo), fp32 accumulate.
//   B staged ONCE in SMEM (full K); A fragments loaded directly from global.
//   CTA tile 64x128 (8 warps, warp tile 16x64), 3 CTAs/SM (24 warps/SM)
//   for latency hiding. ~75 regs/thread under __launch_bounds__(256,3).
// -------------------------------------------------------------------------
#define BSROW  272                    // B row stride bytes (256 + 16)
#define OFF_BH 0
#define OFF_BL (128 * BSROW)          // 34816
#define SMEM_TOT (2 * 128 * BSROW)    // 69632 B -> 3 CTAs/SM (209KB of 228KB)

__global__ void __launch_bounds__(256, 3)
mma_gemm_kernel(const float* __restrict__ Amat,
                const __nv_bfloat16* __restrict__ Bh,
                const __nv_bfloat16* __restrict__ Bl,
                const float* __restrict__ bias,
                const int* __restrict__ ridx,
                float* __restrict__ C, int M) {
    extern __shared__ char smem[];
    uint32_t sb = smem_u32(smem);
    int t = threadIdx.x, lane = t & 31, w = t >> 5;
    int mBase = blockIdx.x * 64;

    // compute mapping: warp (w&3) -> m rows [16), (w>>2) -> n cols [64)
    int warpM = (w & 3) * 16;
    int warpN = (w >> 2) * 64;
    int g = lane >> 2, p = lane & 3;

    // A row pointers: slot 0 = row g, slot 1 = row g+8
    const char* ar[2];
#pragma unroll
    for (int i = 0; i < 2; i++) {
        int m = mBase + warpM + i * 8 + g;
        if (m >= M) m = M - 1;
        int rr = ridx ? ridx[m] : m;
        ar[i] = (const char*)(Amat + (size_t)rr * D);
    }

    // prefetch A k-step 0 (before barrier; independent of SMEM)
    // af[slot]: 0 = row g k-lo, 1 = row g+8 k-lo, 2 = row g k-hi, 3 = row g+8 k-hi
    float2 af[4];
    af[0] = *(const float2*)(ar[0] + p * 8);
    af[1] = *(const float2*)(ar[1] + p * 8);
    af[2] = *(const float2*)(ar[0] + p * 8 + 32);
    af[3] = *(const float2*)(ar[1] + p * 8 + 32);

    // ---- stage B (full K, hi+lo), one time ----
    {
        int row = t >> 1, half = t & 1;
        const uint4* bhp = (const uint4*)(Bh + row * D + half * 64);
        const uint4* blp = (const uint4*)(Bl + row * D + half * 64);
        uint4* dh = (uint4*)(smem + OFF_BH + row * BSROW + half * 128);
        uint4* dl = (uint4*)(smem + OFF_BL + row * BSROW + half * 128);
#pragma unroll
        for (int j = 0; j < 8; j++) {
            dh[j] = bhp[j];
            dl[j] = blp[j];
        }
    }
    __syncthreads();

    int ldRow = (lane & 7) + 8 * ((lane >> 3) & 1);
    int ldK16 = (lane >> 4) * 16;
    uint32_t bOff = sb + (uint32_t)((warpN + ldRow) * BSROW + ldK16);

    float acc[8][4];
#pragma unroll
    for (int nb = 0; nb < 8; nb++)
#pragma unroll
        for (int i = 0; i < 4; i++) acc[nb][i] = 0.f;

#pragma unroll
    for (int ks = 0; ks < 8; ks++) {
        // convert current A fragments to bf16 hi/lo
        uint32_t ah[4], al[4];
#pragma unroll
        for (int s = 0; s < 4; s++) {
            float2 v = af[s];
            ah[s] = pack2(v.x, v.y);
            al[s] = pack2(lo_of(v.x), lo_of(v.y));
        }
        // prefetch next k-step's A
        if (ks < 7) {
            int off = (ks + 1) * 64 + p * 8;
            af[0] = *(const float2*)(ar[0] + off);
            af[1] = *(const float2*)(ar[1] + off);
            af[2] = *(const float2*)(ar[0] + off + 32);
            af[3] = *(const float2*)(ar[1] + off + 32);
        }
        uint32_t kB = ks * 32;
#pragma unroll
        for (int nb2 = 0; nb2 < 4; nb2++) {
            uint32_t base = bOff + (uint32_t)(nb2 * (16 * BSROW)) + kB;
            uint32_t bh[4], bl[4];
            LDSM_X4(bh, base + OFF_BH);
            LDSM_X4(bl, base + OFF_BL);
            int n0 = nb2 * 2, n1 = nb2 * 2 + 1;
            // term hh
            MMA_BF16(acc[n0], ah[0], ah[1], ah[2], ah[3], bh[0], bh[2]);
            MMA_BF16(acc[n1], ah[0], ah[1], ah[2], ah[3], bh[1], bh[3]);
            // term lh
            MMA_BF16(acc[n0], al[0], al[1], al[2], al[3], bh[0], bh[2]);
            MMA_BF16(acc[n1], al[0], al[1], al[2], al[3], bh[1], bh[3]);
            // term hl
            MMA_BF16(acc[n0], ah[0], ah[1], ah[2], ah[3], bl[0], bl[2]);
            MMA_BF16(acc[n1], ah[0], ah[1], ah[2], ah[3], bl[1], bl[3]);
        }
    }

    // ---- epilogue ----
    int r0 = mBase + warpM + g;
    int r1 = r0 + 8;
#pragma unroll
    for (int nb = 0; nb < 8; nb++) {
        int col = warpN + nb * 8 + p * 2;
        float2 bv = *(const float2*)(bias + col);
        if (r0 < M) {
            float2 o = {acc[nb][0] + bv.x, acc[nb][1] + bv.y};
            *(float2*)(C + (size_t)r0 * D + col) = o;
        }
        if (r1 < M) {
            float2 o = {acc[nb][2] + bv.x, acc[nb][3] + bv.y};
            *(float2*)(C + (size_t)r1 * D + col) = o;
        }
    }
}

// -------------------------------------------------------------------------
// 4) fused per-segment online softmax + weighted embedding sum.
//    2 groups per warp (16 lanes each, 8 floats/lane), 4-row unroll.
// -------------------------------------------------------------------------
__global__ void seg_softmax_kernel(const float* __restrict__ emb, int G) {
    int w = (blockIdx.x * blockDim.x + threadIdx.x) >> 5;
    int lane = threadIdx.x & 31;
    if (2 * w >= G) return;
    int sub = lane >> 4, sl = lane & 15;
    int grp = 2 * w + sub;
    bool valid = grp < G;
    int gg = valid ? grp : G - 1;
    unsigned gmask = 0xFFFFu << (sub * 16);

    int start = (gg == 0) ? 0 : (g_last[gg - 1] + 1);
    int end   = g_last[gg];

    const float4* pvp = (const float4*)(g_p + (size_t)gg * D + sl * 8);
    float4 pv0 = pvp[0], pv1 = pvp[1];
    const float4* erow = (const float4*)emb;  // index = r*32 + sl*2 (+1)

    float m = -1e30f, denom = 0.f;
    float4 a0 = {0.f, 0.f, 0.f, 0.f}, a1 = {0.f, 0.f, 0.f, 0.f};

    for (int r = start; r <= end; r += 4) {
        int rr1 = (r + 1 <= end) ? r + 1 : end;
        int rr2 = (r + 2 <= end) ? r + 2 : end;
        int rr3 = (r + 3 <= end) ? r + 3 : end;
        float4 c00 = erow[(size_t)r   * 32 + sl * 2];
        float4 c01 = erow[(size_t)r   * 32 + sl * 2 + 1];
        float4 c10 = erow[(size_t)rr1 * 32 + sl * 2];
        float4 c11 = erow[(size_t)rr1 * 32 + sl * 2 + 1];
        float4 c20 = erow[(size_t)rr2 * 32 + sl * 2];
        float4 c21 = erow[(size_t)rr2 * 32 + sl * 2 + 1];
        float4 c30 = erow[(size_t)rr3 * 32 + sl * 2];
        float4 c31 = erow[(size_t)rr3 * 32 + sl * 2 + 1];

        float q0 = c00.x * pv0.x + c00.y * pv0.y + c00.z * pv0.z + c00.w * pv0.w
                 + c01.x * pv1.x + c01.y * pv1.y + c01.z * pv1.z + c01.w * pv1.w;
        float q1 = c10.x * pv0.x + c10.y * pv0.y + c10.z * pv0.z + c10.w * pv0.w
                 + c11.x * pv1.x + c11.y * pv1.y + c11.z * pv1.z + c11.w * pv1.w;
        float q2 = c20.x * pv0.x + c20.y * pv0.y + c20.z * pv0.z + c20.w * pv0.w
                 + c21.x * pv1.x + c21.y * pv1.y + c21.z * pv1.z + c21.w * pv1.w;
        float q3 = c30.x * pv0.x + c30.y * pv0.y + c30.z * pv0.z + c30.w * pv0.w
                 + c31.x * pv1.x + c31.y * pv1.y + c31.z * pv1.z + c31.w * pv1.w;
#pragma unroll
        for (int off = 8; off > 0; off >>= 1) {
            q0 += __shfl_xor_sync(gmask, q0, off);
            q1 += __shfl_xor_sync(gmask, q1, off);
            q2 += __shfl_xor_sync(gmask, q2, off);
            q3 += __shfl_xor_sync(gmask, q3, off);
        }
        if (r + 1 > end) q1 = -1e30f;
        if (r + 2 > end) q2 = -1e30f;
        if (r + 3 > end) q3 = -1e30f;

        float mnew = fmaxf(fmaxf(fmaxf(m, q0), fmaxf(q1, q2)), q3);
        float sc = __expf(m - mnew);
        float w0 = __expf(q0 - mnew);
        float w1 = __expf(q1 - mnew);
        float w2 = __expf(q2 - mnew);
        float w3 = __expf(q3 - mnew);
        denom = denom * sc + ((w0 + w1) + (w2 + w3));
        a0.x = a0.x * sc + w0 * c00.x + w1 * c10.x + w2 * c20.x + w3 * c30.x;
        a0.y = a0.y * sc + w0 * c00.y + w1 * c10.y + w2 * c20.y + w3 * c30.y;
        a0.z = a0.z * sc + w0 * c00.z + w1 * c10.z + w2 * c20.z + w3 * c30.z;
        a0.w = a0.w * sc + w0 * c00.w + w1 * c10.w + w2 * c20.w + w3 * c30.w;
        a1.x = a1.x * sc + w0 * c01.x + w1 * c11.x + w2 * c21.x + w3 * c31.x;
        a1.y = a1.y * sc + w0 * c01.y + w1 * c11.y + w2 * c21.y + w3 * c31.y;
        a1.z = a1.z * sc + w0 * c01.z + w1 * c11.z + w2 * c21.z + w3 * c31.z;
        a1.w = a1.w * sc + w0 * c01.w + w1 * c11.w + w2 * c21.w + w3 * c31.w;
        m = mnew;
    }

    if (valid) {
        float inv = 1.0f / denom;
        float4 o0 = {a0.x * inv, a0.y * inv, a0.z * inv, a0.w * inv};
        float4 o1 = {a1.x * inv, a1.y * inv, a1.z * inv, a1.w * inv};
        float4* sp = (float4*)(g_s + (size_t)gg * D + sl * 8);
        sp[0] = o0;
        sp[1] = o1;
    }
}

// -------------------------------------------------------------------------
extern "C" void kernel_launch(void* const* d_in, const int* in_sizes, int n_in,
                              void* d_out, int out_size) {
    const float* emb = (const float*)d_in[0];
    const int*   seg = (const int*)d_in[1];
    const float* Wq  = (const float*)d_in[2];
    const float* bq  = (const float*)d_in[3];
    const float* Wk  = (const float*)d_in[4];
    const float* bk  = (const float*)d_in[5];
    float* out = (float*)d_out;

    int N = in_sizes[0] / D;
    int G = out_size / D;

    static bool attr_done = false;
    if (!attr_done) {
        cudaFuncSetAttribute(mma_gemm_kernel,
                             cudaFuncAttributeMaxDynamicSharedMemorySize, SMEM_TOT);
        attr_done = true;
    }

    void *pLast, *pBp, *pP, *pS, *pB1h, *pB1l, *pB2h, *pB2l;
    cudaGetSymbolAddress(&pLast, g_last);
    cudaGetSymbolAddress(&pBp, g_bp);
    cudaGetSymbolAddress(&pP, g_p);
    cudaGetSymbolAddress(&pS, g_s);
    cudaGetSymbolAddress(&pB1h, g_B1h);
    cudaGetSymbolAddress(&pB1l, g_B1l);
    cudaGetSymbolAddress(&pB2h, g_B2h);
    cudaGetSymbolAddress(&pB2l, g_B2l);

    bounds_kernel<<<(N + 255) / 256, 256>>>(seg, N);
    prep_kernel<<<65, 256>>>(Wq, bq, Wk);
    split_kernel<<<64, 256>>>(Wk);

    int nblk = (G + 63) / 64;

    // p[G,128] = emb[last] @ Aqk + b'
    mma_gemm_kernel<<<nblk, 256, SMEM_TOT>>>(
        emb, (const __nv_bfloat16*)pB1h, (const __nv_bfloat16*)pB1l,
        (const float*)pBp, (const int*)pLast, (float*)pP, G);

    // fused segment softmax -> s[G,128]  (2 groups per warp)
    seg_softmax_kernel<<<(G + 15) / 16, 256>>>(emb, G);

    // out = s @ Wk^T + bk
    mma_gemm_kernel<<<nblk, 256, SMEM_TOT>>>(
        (const float*)pS, (const __nv_bfloat16*)pB2h, (const __nv_bfloat16*)pB2l,
        bk, nullptr, out, G);
}

// round 17
// speedup vs baseline: 1.1313x; 1.1313x over previous
#include <cuda_runtime.h>
#include <cuda_bf16.h>
#include <cstddef>
#include <cstdint>

#define D 128
#define MAXG 100000
#define NSLICE 4

// scratch (device globals — no allocation allowed)
__device__ int   g_last[MAXG];
__device__ float g_A[D * D];
__device__ float g_bp[D];
__device__ float g_p[(size_t)MAXG * D];
__device__ float g_s[(size_t)MAXG * D];
// bf16 hi/lo splits of the two B matrices, stored as b_eff[n][k]
__device__ __nv_bfloat16 g_B1h[D * D], g_B1l[D * D];
__device__ __nv_bfloat16 g_B2h[D * D], g_B2l[D * D];

// ---------------------------------------------------------------- helpers
__device__ __forceinline__ float lo_of(float v) {
    return v - __bfloat162float(__float2bfloat16(v));
}
__device__ __forceinline__ uint32_t pack2(float a, float b) {
    __nv_bfloat162 h;
    h.x = __float2bfloat16(a);
    h.y = __float2bfloat16(b);
    return *(uint32_t*)&h;
}
__device__ __forceinline__ uint32_t smem_u32(const void* p) {
    uint32_t a;
    asm("{ .reg .u64 t; cvta.to.shared.u64 t, %1; cvt.u32.u64 %0, t; }"
        : "=r"(a) : "l"(p));
    return a;
}

#define MMA_BF16(cc, a0, a1, a2, a3, b0, b1)                                  \
    asm volatile(                                                             \
        "mma.sync.aligned.m16n8k16.row.col.f32.bf16.bf16.f32 "                \
        "{%0,%1,%2,%3}, {%4,%5,%6,%7}, {%8,%9}, {%0,%1,%2,%3};"               \
        : "+f"(cc[0]), "+f"(cc[1]), "+f"(cc[2]), "+f"(cc[3])                  \
        : "r"(a0), "r"(a1), "r"(a2), "r"(a3), "r"(b0), "r"(b1))

#define LDSM_X4(r, addr)                                                      \
    asm volatile("ldmatrix.sync.aligned.m8n8.x4.shared.b16 {%0,%1,%2,%3}, [%4];" \
                 : "=r"(r[0]), "=r"(r[1]), "=r"(r[2]), "=r"(r[3])             \
                 : "r"(addr))

// -------------------------------------------------------------------------
// 1) segment boundaries
// -------------------------------------------------------------------------
__global__ void bounds_kernel(const int* __restrict__ seg, int N) {
    int i = blockIdx.x * blockDim.x + threadIdx.x;
    if (i < N) {
        int sid = seg[i];
        if (i == N - 1 || seg[i + 1] != sid) g_last[sid] = i;
    }
}

// -------------------------------------------------------------------------
// 2) A = Wq^T @ Wk, b' = bq @ Wk
// -------------------------------------------------------------------------
__global__ void prep_kernel(const float* __restrict__ Wq, const float* __restrict__ bq,
                            const float* __restrict__ Wk) {
    int t = threadIdx.x;
    if (blockIdx.x < 64) {
        int idx = blockIdx.x * 256 + t;
        int i = idx >> 7, j = idx & 127;
        float sum = 0.f;
#pragma unroll 8
        for (int d = 0; d < D; d++) sum += Wq[d * D + i] * Wk[d * D + j];
        g_A[idx] = sum;
    } else if (t < D) {
        float sum = 0.f;
#pragma unroll 8
        for (int d = 0; d < D; d++) sum += bq[d] * Wk[d * D + t];
        g_bp[t] = sum;
    }
}

// -------------------------------------------------------------------------
// 2b) bf16 hi/lo split of both B matrices (b_eff[n][k] layout)
// -------------------------------------------------------------------------
__global__ void split_kernel(const float* __restrict__ Wk) {
    int idx = blockIdx.x * 256 + threadIdx.x;
    int n = idx >> 7, k = idx & 127;
    float v1 = g_A[k * D + n];
    g_B1h[idx] = __float2bfloat16(v1);
    g_B1l[idx] = __float2bfloat16(lo_of(v1));
    float v2 = Wk[idx];
    g_B2h[idx] = __float2bfloat16(v2);
    g_B2l[idx] = __float2bfloat16(lo_of(v2));
}

// -------------------------------------------------------------------------
// Tensor-core GEMM via mma.sync + ldmatrix (R6 config, sliced):
//   C[m0..m1,128] = rows(Amat) @ b_eff^T + bias
//   3-term bf16 split, fp32 accumulate. CTA tile 128x128, K chunked at 64,
//   256 thr, warp tile 32x64, 2 CTAs/SM.
// -------------------------------------------------------------------------
#define KC   64
#define SROW 144
#define OFF_AH 0
#define OFF_AL (128 * SROW)
#define OFF_BH (2 * 128 * SROW)
#define OFF_BL (3 * 128 * SROW)
#define SMEM_TOT (4 * 128 * SROW)     // 73728 B

__global__ void __launch_bounds__(256, 2)
mma_gemm_kernel(const float* __restrict__ Amat,
                const __nv_bfloat16* __restrict__ Bh,
                const __nv_bfloat16* __restrict__ Bl,
                const float* __restrict__ bias,
                const int* __restrict__ ridx,
                float* __restrict__ C, int mStart, int mEnd) {
    extern __shared__ char smem[];
    uint32_t sb = smem_u32(smem);
    int t = threadIdx.x, lane = t & 31, w = t >> 5;
    int mBase = mStart + blockIdx.x * 128;

    // staging mapping: 2 threads per row, 32 k-elements each
    int row = t >> 1;
    int kh = (t & 1) * 32;
    int m = mBase + row;
    if (m >= mEnd) m = mEnd - 1;
    int arr = ridx ? ridx[m] : m;
    const float* ap = Amat + (size_t)arr * D + kh;
    const __nv_bfloat16* bhp = Bh + row * D + kh;
    const __nv_bfloat16* blp = Bl + row * D + kh;
    char* sA_h = smem + OFF_AH + row * SROW + kh * 2;
    char* sA_l = smem + OFF_AL + row * SROW + kh * 2;
    char* sB_h = smem + OFF_BH + row * SROW + kh * 2;
    char* sB_l = smem + OFF_BL + row * SROW + kh * 2;

    // compute mapping: warp (w&3) -> m rows [32), (w>>2) -> n cols [64)
    int warpM = (w & 3) * 32;
    int warpN = (w >> 2) * 64;
    int ldRow = ((lane >> 3) & 1) * 8 + (lane & 7);
    int ldK16 = (lane >> 4) * 16;
    uint32_t aOff = (uint32_t)((warpM + ldRow) * SROW + ldK16);
    uint32_t bOff = (uint32_t)((warpN + ldRow) * SROW + ldK16);

    float acc[2][8][4];
#pragma unroll
    for (int mb = 0; mb < 2; mb++)
#pragma unroll
        for (int nb = 0; nb < 8; nb++)
#pragma unroll
            for (int i = 0; i < 4; i++) acc[mb][nb][i] = 0.f;

#pragma unroll 1
    for (int kc = 0; kc < 2; kc++) {
        if (kc) __syncthreads();
        // ---- stage chunk kc ----
        {
            const float* a = ap + kc * KC;
#pragma unroll
            for (int j = 0; j < 4; j++) {
                float4 v0 = *(const float4*)(a + j * 8);
                float4 v1 = *(const float4*)(a + j * 8 + 4);
                uint4 hi = {pack2(v0.x, v0.y), pack2(v0.z, v0.w),
                            pack2(v1.x, v1.y), pack2(v1.z, v1.w)};
                uint4 lo = {pack2(lo_of(v0.x), lo_of(v0.y)), pack2(lo_of(v0.z), lo_of(v0.w)),
                            pack2(lo_of(v1.x), lo_of(v1.y)), pack2(lo_of(v1.z), lo_of(v1.w))};
                *(uint4*)(sA_h + j * 16) = hi;
                *(uint4*)(sA_l + j * 16) = lo;
                *(uint4*)(sB_h + j * 16) = *(const uint4*)(bhp + kc * KC + j * 8);
                *(uint4*)(sB_l + j * 16) = *(const uint4*)(blp + kc * KC + j * 8);
            }
        }
        __syncthreads();

        // ---- compute 4 k-steps of this chunk ----
#pragma unroll
        for (int ks = 0; ks < 4; ks++) {
            uint32_t kOffB = ks * 32;
            uint32_t ah[2][4], al[2][4];
#pragma unroll
            for (int mb = 0; mb < 2; mb++) {
                uint32_t base = aOff + mb * (16 * SROW) + kOffB;
                LDSM_X4(ah[mb], sb + OFF_AH + base);
                LDSM_X4(al[mb], sb + OFF_AL + base);
            }
#pragma unroll
            for (int nb2 = 0; nb2 < 4; nb2++) {
                uint32_t base = bOff + nb2 * (16 * SROW) + kOffB;
                uint32_t bh[4], bl[4];
                LDSM_X4(bh, sb + OFF_BH + base);
                LDSM_X4(bl, sb + OFF_BL + base);
#pragma unroll
                for (int mb = 0; mb < 2; mb++) {
                    MMA_BF16(acc[mb][nb2 * 2],     ah[mb][0], ah[mb][1], ah[mb][2], ah[mb][3], bh[0], bh[2]);
                    MMA_BF16(acc[mb][nb2 * 2],     al[mb][0], al[mb][1], al[mb][2], al[mb][3], bh[0], bh[2]);
                    MMA_BF16(acc[mb][nb2 * 2],     ah[mb][0], ah[mb][1], ah[mb][2], ah[mb][3], bl[0], bl[2]);
                    MMA_BF16(acc[mb][nb2 * 2 + 1], ah[mb][0], ah[mb][1], ah[mb][2], ah[mb][3], bh[1], bh[3]);
                    MMA_BF16(acc[mb][nb2 * 2 + 1], al[mb][0], al[mb][1], al[mb][2], al[mb][3], bh[1], bh[3]);
                    MMA_BF16(acc[mb][nb2 * 2 + 1], ah[mb][0], ah[mb][1], ah[mb][2], ah[mb][3], bl[1], bl[3]);
                }
            }
        }
    }

    // ---- epilogue ----
    int g = lane >> 2, p = lane & 3;
#pragma unroll
    for (int mb = 0; mb < 2; mb++) {
        int r0 = mBase + warpM + mb * 16 + g;
        int r1 = r0 + 8;
#pragma unroll
        for (int nb = 0; nb < 8; nb++) {
            int col = warpN + nb * 8 + p * 2;
            float2 bv = *(const float2*)(bias + col);
            if (r0 < mEnd) {
                float2 o = {acc[mb][nb][0] + bv.x, acc[mb][nb][1] + bv.y};
                *(float2*)(C + (size_t)r0 * D + col) = o;
            }
            if (r1 < mEnd) {
                float2 o = {acc[mb][nb][2] + bv.x, acc[mb][nb][3] + bv.y};
                *(float2*)(C + (size_t)r1 * D + col) = o;
            }
        }
    }
}

// -------------------------------------------------------------------------
// 4) fused per-segment online softmax + weighted embedding sum (sliced).
//    2 groups per warp (16 lanes each, 8 floats/lane), 4-row unroll.
// -------------------------------------------------------------------------
__global__ void seg_softmax_kernel(const float* __restrict__ emb, int gStart, int gEnd) {
    int w = (blockIdx.x * blockDim.x + threadIdx.x) >> 5;
    int lane = threadIdx.x & 31;
    int sub = lane >> 4, sl = lane & 15;
    int grp = gStart + 2 * w + sub;
    if (gStart + 2 * w >= gEnd) return;
    bool valid = grp < gEnd;
    int gg = valid ? grp : gEnd - 1;
    unsigned gmask = 0xFFFFu << (sub * 16);

    int start = (gg == 0) ? 0 : (g_last[gg - 1] + 1);
    int end   = g_last[gg];

    const float4* pvp = (const float4*)(g_p + (size_t)gg * D + sl * 8);
    float4 pv0 = pvp[0], pv1 = pvp[1];
    const float4* erow = (const float4*)emb;  // index = r*32 + sl*2 (+1)

    float m = -1e30f, denom = 0.f;
    float4 a0 = {0.f, 0.f, 0.f, 0.f}, a1 = {0.f, 0.f, 0.f, 0.f};

    for (int r = start; r <= end; r += 4) {
        int rr1 = (r + 1 <= end) ? r + 1 : end;
        int rr2 = (r + 2 <= end) ? r + 2 : end;
        int rr3 = (r + 3 <= end) ? r + 3 : end;
        float4 c00 = erow[(size_t)r   * 32 + sl * 2];
        float4 c01 = erow[(size_t)r   * 32 + sl * 2 + 1];
        float4 c10 = erow[(size_t)rr1 * 32 + sl * 2];
        float4 c11 = erow[(size_t)rr1 * 32 + sl * 2 + 1];
        float4 c20 = erow[(size_t)rr2 * 32 + sl * 2];
        float4 c21 = erow[(size_t)rr2 * 32 + sl * 2 + 1];
        float4 c30 = erow[(size_t)rr3 * 32 + sl * 2];
        float4 c31 = erow[(size_t)rr3 * 32 + sl * 2 + 1];

        float q0 = c00.x * pv0.x + c00.y * pv0.y + c00.z * pv0.z + c00.w * pv0.w
                 + c01.x * pv1.x + c01.y * pv1.y + c01.z * pv1.z + c01.w * pv1.w;
        float q1 = c10.x * pv0.x + c10.y * pv0.y + c10.z * pv0.z + c10.w * pv0.w
                 + c11.x * pv1.x + c11.y * pv1.y + c11.z * pv1.z + c11.w * pv1.w;
        float q2 = c20.x * pv0.x + c20.y * pv0.y + c20.z * pv0.z + c20.w * pv0.w
                 + c21.x * pv1.x + c21.y * pv1.y + c21.z * pv1.z + c21.w * pv1.w;
        float q3 = c30.x * pv0.x + c30.y * pv0.y + c30.z * pv0.z + c30.w * pv0.w
                 + c31.x * pv1.x + c31.y * pv1.y + c31.z * pv1.z + c31.w * pv1.w;
#pragma unroll
        for (int off = 8; off > 0; off >>= 1) {
            q0 += __shfl_xor_sync(gmask, q0, off);
            q1 += __shfl_xor_sync(gmask, q1, off);
            q2 += __shfl_xor_sync(gmask, q2, off);
            q3 += __shfl_xor_sync(gmask, q3, off);
        }
        if (r + 1 > end) q1 = -1e30f;
        if (r + 2 > end) q2 = -1e30f;
        if (r + 3 > end) q3 = -1e30f;

        float mnew = fmaxf(fmaxf(fmaxf(m, q0), fmaxf(q1, q2)), q3);
        float sc = __expf(m - mnew);
        float w0 = __expf(q0 - mnew);
        float w1 = __expf(q1 - mnew);
        float w2 = __expf(q2 - mnew);
        float w3 = __expf(q3 - mnew);
        denom = denom * sc + ((w0 + w1) + (w2 + w3));
        a0.x = a0.x * sc + w0 * c00.x + w1 * c10.x + w2 * c20.x + w3 * c30.x;
        a0.y = a0.y * sc + w0 * c00.y + w1 * c10.y + w2 * c20.y + w3 * c30.y;
        a0.z = a0.z * sc + w0 * c00.z + w1 * c10.z + w2 * c20.z + w3 * c30.z;
        a0.w = a0.w * sc + w0 * c00.w + w1 * c10.w + w2 * c20.w + w3 * c30.w;
        a1.x = a1.x * sc + w0 * c01.x + w1 * c11.x + w2 * c21.x + w3 * c31.x;
        a1.y = a1.y * sc + w0 * c01.y + w1 * c11.y + w2 * c21.y + w3 * c31.y;
        a1.z = a1.z * sc + w0 * c01.z + w1 * c11.z + w2 * c21.z + w3 * c31.z;
        a1.w = a1.w * sc + w0 * c01.w + w1 * c11.w + w2 * c21.w + w3 * c31.w;
        m = mnew;
    }

    if (valid) {
        float inv = 1.0f / denom;
        float4 o0 = {a0.x * inv, a0.y * inv, a0.z * inv, a0.w * inv};
        float4 o1 = {a1.x * inv, a1.y * inv, a1.z * inv, a1.w * inv};
        float4* sp = (float4*)(g_s + (size_t)gg * D + sl * 8);
        sp[0] = o0;
        sp[1] = o1;
    }
}

// -------------------------------------------------------------------------
extern "C" void kernel_launch(void* const* d_in, const int* in_sizes, int n_in,
                              void* d_out, int out_size) {
    const float* emb = (const float*)d_in[0];
    const int*   seg = (const int*)d_in[1];
    const float* Wq  = (const float*)d_in[2];
    const float* bq  = (const float*)d_in[3];
    const float* Wk  = (const float*)d_in[4];
    const float* bk  = (const float*)d_in[5];
    float* out = (float*)d_out;

    int N = in_sizes[0] / D;
    int G = out_size / D;

    static cudaStream_t s1 = nullptr;
    static cudaEvent_t evFork, evPrep, evG1[NSLICE], evS[NSLICE];
    if (s1 == nullptr) {
        cudaStreamCreateWithFlags(&s1, cudaStreamNonBlocking);
        cudaEventCreateWithFlags(&evFork, cudaEventDisableTiming);
        cudaEventCreateWithFlags(&evPrep, cudaEventDisableTiming);
        for (int i = 0; i < NSLICE; i++) {
            cudaEventCreateWithFlags(&evG1[i], cudaEventDisableTiming);
            cudaEventCreateWithFlags(&evS[i], cudaEventDisableTiming);
        }
        cudaFuncSetAttribute(mma_gemm_kernel,
                             cudaFuncAttributeMaxDynamicSharedMemorySize, SMEM_TOT);
    }

    void *pLast, *pBp, *pP, *pS, *pB1h, *pB1l, *pB2h, *pB2l;
    cudaGetSymbolAddress(&pLast, g_last);
    cudaGetSymbolAddress(&pBp, g_bp);
    cudaGetSymbolAddress(&pP, g_p);
    cudaGetSymbolAddress(&pS, g_s);
    cudaGetSymbolAddress(&pB1h, g_B1h);
    cudaGetSymbolAddress(&pB1l, g_B1l);
    cudaGetSymbolAddress(&pB2h, g_B2h);
    cudaGetSymbolAddress(&pB2l, g_B2l);

    // slice boundaries (multiples of 128 groups)
    int SL = ((G / NSLICE + 127) / 128) * 128;
    int g0s[NSLICE], g1s[NSLICE];
    for (int i = 0; i < NSLICE; i++) {
        g0s[i] = i * SL;
        int e = (i + 1) * SL;
        g1s[i] = e < G ? e : G;
        if (g0s[i] > G) g0s[i] = G;
    }

    // fork: prep + split run on s1, concurrent with bounds on stream 0
    cudaEventRecord(evFork, 0);
    cudaStreamWaitEvent(s1, evFork, 0);
    prep_kernel<<<65, 256, 0, s1>>>(Wq, bq, Wk);
    split_kernel<<<64, 256, 0, s1>>>(Wk);
    cudaEventRecord(evPrep, s1);

    bounds_kernel<<<(N + 255) / 256, 256>>>(seg, N);
    cudaStreamWaitEvent(0, evPrep, 0);

    // GEMM1 slices on stream 0
    for (int i = 0; i < NSLICE; i++) {
        int cnt = g1s[i] - g0s[i];
        if (cnt <= 0) { cudaEventRecord(evG1[i], 0); continue; }
        mma_gemm_kernel<<<(cnt + 127) / 128, 256, SMEM_TOT>>>(
            emb, (const __nv_bfloat16*)pB1h, (const __nv_bfloat16*)pB1l,
            (const float*)pBp, (const int*)pLast, (float*)pP, g0s[i], g1s[i]);
        cudaEventRecord(evG1[i], 0);
    }

    // softmax slices on s1, each gated on its GEMM1 slice
    for (int i = 0; i < NSLICE; i++) {
        int cnt = g1s[i] - g0s[i];
        cudaStreamWaitEvent(s1, evG1[i], 0);
        if (cnt > 0) {
            seg_softmax_kernel<<<(cnt + 15) / 16, 256, 0, s1>>>(emb, g0s[i], g1s[i]);
        }
        cudaEventRecord(evS[i], s1);
    }

    // GEMM2 slices on stream 0, each gated on its softmax slice
    for (int i = 0; i < NSLICE; i++) {
        int cnt = g1s[i] - g0s[i];
        cudaStreamWaitEvent(0, evS[i], 0);
        if (cnt <= 0) continue;
        mma_gemm_kernel<<<(cnt + 127) / 128, 256, SMEM_TOT>>>(
            (const float*)pS, (const __nv_bfloat16*)pB2h, (const __nv_bfloat16*)pB2l,
            bk, nullptr, out, g0s[i], g1s[i]);
    }
}